// round 16
// baseline (speedup 1.0000x reference)
#include <cuda_runtime.h>
#include <cstdint>

#define N_ROWS   65536
#define KCODES   1024
#define DDIM     256
#define B_STRIDE 262144

#define OFF_LOSS 0ll
#define OFF_QOUT 1ll
#define OFF_PERP 16777217ll
#define OFF_ENC  16777218ll
#define OFF_QF   83886082ll

#define MARGIN 1.0e-4f
#define BIGF   3.4e38f

// ---------------- device scratch ----------------
__device__ float  g_nf[N_ROWS];
__device__ float  g_ne[KCODES];
__device__ int    g_idx[N_ROWS];
__device__ int    g_counts[KCODES];
__device__ double g_loss_acc;
__device__ float2 g_cv[N_ROWS * 16];  // per-row, per 64-code half-block top-2 dists
__device__ int2   g_ci[N_ROWS * 16];  // matching code indices
__device__ int    g_wlA[N_ROWS];
__device__ int    g_wlB[N_ROWS];
__device__ int    g_nA, g_nB;

__device__ __forceinline__ uint32_t cvt_tf32(float x) {
    uint32_t r; asm("cvt.rna.tf32.f32 %0, %1;" : "=r"(r) : "f"(x)); return r;
}
__device__ __forceinline__ void mma8(float* c, const uint32_t* a, uint32_t b0, uint32_t b1) {
    asm volatile(
        "mma.sync.aligned.m16n8k8.row.col.f32.tf32.tf32.f32 "
        "{%0,%1,%2,%3}, {%4,%5,%6,%7}, {%8,%9}, {%0,%1,%2,%3};"
        : "+f"(c[0]), "+f"(c[1]), "+f"(c[2]), "+f"(c[3])
        : "r"(a[0]), "r"(a[1]), "r"(a[2]), "r"(a[3]), "r"(b0), "r"(b1));
}
// exact distance formula — bit-identical to the proven R2 kernel
__device__ __forceinline__ float distf(float nf, float ne, float c) {
    return __fsub_rn(__fadd_rn(nf, ne), __fmul_rn(2.0f, c));
}

// ---------------- init ----------------
__global__ void k_init() {
    int g = blockIdx.x * blockDim.x + threadIdx.x;
    if (g < KCODES) g_counts[g] = 0;
    if (g == 0) { g_loss_acc = 0.0; g_nA = 0; g_nB = 0; }
}

// ---------------- ||e_k||^2 ----------------
__global__ void k_ne(const float* __restrict__ emb) {
    int w = blockIdx.x * 8 + (threadIdx.x >> 5);
    int lane = threadIdx.x & 31;
    const float* e = emb + (size_t)w * DDIM;
    float s = 0.f;
#pragma unroll
    for (int j = 0; j < 8; j++) { float v = e[lane + 32 * j]; s = __fadd_rn(s, __fmul_rn(v, v)); }
#pragma unroll
    for (int off = 16; off; off >>= 1) s = __fadd_rn(s, __shfl_down_sync(0xffffffffu, s, off));
    if (lane == 0) g_ne[w] = s;
}

// ---------------- ||f_n||^2 ----------------
__global__ void __launch_bounds__(256) k_nf(const float* __restrict__ inp) {
    int r = blockIdx.x * 256 + threadIdx.x;
    int b = r >> 10, hw = r & 1023;
    const float* p = inp + (size_t)b * B_STRIDE + hw;
    float acc[16];
#pragma unroll
    for (int j = 0; j < 16; j++) acc[j] = 0.f;
    for (int s = 0; s < 16; s++)
#pragma unroll
        for (int j = 0; j < 16; j++) {
            float v = p[(size_t)(s * 16 + j) * 1024];
            acc[j] = __fadd_rn(acc[j], __fmul_rn(v, v));
        }
#pragma unroll
    for (int s2 = 8; s2; s2 >>= 1)
#pragma unroll
        for (int j = 0; j < 8; j++)
            if (j < s2) acc[j] = __fadd_rn(acc[j], acc[j + s2]);
    g_nf[r] = acc[0];
}

// ---------------- 3xTF32 mma.sync distance-GEMM -> per-half-block top-2 -----
#define PADW 136
#define SM_FLOATS (4 * 32 * PADW)

__global__ void __launch_bounds__(256) k_gemm(const float* __restrict__ inp,
                                              const float* __restrict__ emb) {
    extern __shared__ float sm[];
    float* Ah = sm;
    float* Al = sm + 32 * PADW;
    float* Bh = sm + 2 * 32 * PADW;
    float* Bl = sm + 3 * 32 * PADW;

    const int tid = threadIdx.x, lane = tid & 31, wid = tid >> 5;
    const int wm = wid & 3, wn = wid >> 2;
    const int cb = blockIdx.x, rblk = blockIdx.y;
    const int b = (rblk * 128) >> 10, hw0 = (rblk * 128) & 1023;
    const float* aG = inp + (size_t)b * B_STRIDE + hw0;
    const float* bG = emb + (size_t)cb * 128 * 256;

    float acc[2][8][4];
#pragma unroll
    for (int mt = 0; mt < 2; mt++)
#pragma unroll
        for (int nt = 0; nt < 8; nt++)
#pragma unroll
            for (int e = 0; e < 4; e++) acc[mt][nt][e] = 0.f;

    const int lr4 = (tid & 31) << 2;
    const int lk  = tid >> 5;
    const int bn  = tid >> 1;
    const int bk0 = (tid & 1) << 4;
    const int aoff = (lane & 3) * PADW + wm * 32 + (lane >> 2);
    const int boff = (lane & 3) * PADW + wn * 64 + (lane >> 2);

    for (int kt = 0; kt < 8; kt++) {
#pragma unroll
        for (int i = 0; i < 4; i++) {
            int k = lk + i * 8;
            float4 v = *reinterpret_cast<const float4*>(
                aG + (size_t)(kt * 32 + k) * 1024 + lr4);
            uint32_t hx = cvt_tf32(v.x), hy = cvt_tf32(v.y),
                     hz = cvt_tf32(v.z), hw = cvt_tf32(v.w);
            float4 h = make_float4(__uint_as_float(hx), __uint_as_float(hy),
                                   __uint_as_float(hz), __uint_as_float(hw));
            float4 l = make_float4(
                __uint_as_float(cvt_tf32(__fsub_rn(v.x, h.x))),
                __uint_as_float(cvt_tf32(__fsub_rn(v.y, h.y))),
                __uint_as_float(cvt_tf32(__fsub_rn(v.z, h.z))),
                __uint_as_float(cvt_tf32(__fsub_rn(v.w, h.w))));
            *reinterpret_cast<float4*>(&Ah[k * PADW + lr4]) = h;
            *reinterpret_cast<float4*>(&Al[k * PADW + lr4]) = l;
        }
#pragma unroll
        for (int j = 0; j < 4; j++) {
            float4 v = *reinterpret_cast<const float4*>(
                bG + (size_t)bn * 256 + kt * 32 + bk0 + j * 4);
            int k = bk0 + j * 4;
            float fx[4] = {v.x, v.y, v.z, v.w};
#pragma unroll
            for (int e = 0; e < 4; e++) {
                uint32_t h = cvt_tf32(fx[e]);
                Bh[(k + e) * PADW + bn] = __uint_as_float(h);
                Bl[(k + e) * PADW + bn] =
                    __uint_as_float(cvt_tf32(__fsub_rn(fx[e], __uint_as_float(h))));
            }
        }
        __syncthreads();
#pragma unroll
        for (int k8 = 0; k8 < 4; k8++) {
            const int kb = k8 * 8 * PADW;
            uint32_t ah[2][4], al[2][4];
#pragma unroll
            for (int mt = 0; mt < 2; mt++) {
                int o = kb + aoff + mt * 16;
                ah[mt][0] = __float_as_uint(Ah[o]);
                ah[mt][1] = __float_as_uint(Ah[o + 8]);
                ah[mt][2] = __float_as_uint(Ah[o + 4 * PADW]);
                ah[mt][3] = __float_as_uint(Ah[o + 4 * PADW + 8]);
                al[mt][0] = __float_as_uint(Al[o]);
                al[mt][1] = __float_as_uint(Al[o + 8]);
                al[mt][2] = __float_as_uint(Al[o + 4 * PADW]);
                al[mt][3] = __float_as_uint(Al[o + 4 * PADW + 8]);
            }
#pragma unroll
            for (int nt = 0; nt < 8; nt++) {
                int o = kb + boff + nt * 8;
                uint32_t bh0 = __float_as_uint(Bh[o]);
                uint32_t bh1 = __float_as_uint(Bh[o + 4 * PADW]);
                uint32_t bl0 = __float_as_uint(Bl[o]);
                uint32_t bl1 = __float_as_uint(Bl[o + 4 * PADW]);
#pragma unroll
                for (int mt = 0; mt < 2; mt++) {
                    mma8(acc[mt][nt], ah[mt], bh0, bh1);
                    mma8(acc[mt][nt], al[mt], bh0, bh1);
                    mma8(acc[mt][nt], ah[mt], bl0, bl1);
                }
            }
        }
        __syncthreads();
    }

    float* sNe = sm;
    if (tid < 128) sNe[tid] = g_ne[cb * 128 + tid];
    __syncthreads();

    // epilogue: per-row top-2 over THIS warp's 64-code half; slot keyed by
    // (cb, wn) so the two column-half warps never collide (R10 race fix).
#pragma unroll
    for (int mt = 0; mt < 2; mt++)
#pragma unroll
        for (int half = 0; half < 2; half++) {
            int rl   = wm * 32 + mt * 16 + (lane >> 2) + half * 8;
            int grow = rblk * 128 + rl;
            float nfv = g_nf[grow];
            float v1 = BIGF, v2 = BIGF;
            int   i1 = 1 << 30, i2 = 1 << 30;
#pragma unroll
            for (int nt = 0; nt < 8; nt++)
#pragma unroll
                for (int e = 0; e < 2; e++) {
                    int cl = wn * 64 + nt * 8 + (lane & 3) * 2 + e;
                    float s = distf(nfv, sNe[cl], acc[mt][nt][half * 2 + e]);
                    int   c = cb * 128 + cl;
                    if (s < v1)      { v2 = v1; i2 = i1; v1 = s; i1 = c; }
                    else if (s < v2) { v2 = s; i2 = c; }
                }
#pragma unroll
            for (int off = 1; off < 4; off <<= 1) {
                float w1 = __shfl_down_sync(0xffffffffu, v1, off, 4);
                float w2 = __shfl_down_sync(0xffffffffu, v2, off, 4);
                int   j1 = __shfl_down_sync(0xffffffffu, i1, off, 4);
                int   j2 = __shfl_down_sync(0xffffffffu, i2, off, 4);
                if (w1 < v1 || (w1 == v1 && j1 < i1)) {
                    if (v1 < w2 || (v1 == w2 && i1 < j2)) { v2 = v1; i2 = i1; }
                    else                                  { v2 = w2; i2 = j2; }
                    v1 = w1; i1 = j1;
                } else {
                    if (w1 < v2 || (w1 == v2 && j1 < i2)) { v2 = w1; i2 = j1; }
                }
            }
            if ((lane & 3) == 0) {
                int slot = grow * 16 + cb * 2 + wn;
                g_cv[slot] = make_float2(v1, v2);
                g_ci[slot] = make_int2(i1, i2);
            }
        }
}

// ---------------- pick: resolve unambiguous rows, build worklists -----------
__global__ void __launch_bounds__(256) k_pick() {
    int row = blockIdx.x * 256 + threadIdx.x;
    float vmin = BIGF; int imin = 1 << 30;
    float2 cv[16]; int2 ci[16];
#pragma unroll
    for (int c = 0; c < 16; c++) { cv[c] = g_cv[row * 16 + c]; ci[c] = g_ci[row * 16 + c]; }
#pragma unroll
    for (int c = 0; c < 16; c++) {
        if (cv[c].x < vmin || (cv[c].x == vmin && ci[c].x < imin)) { vmin = cv[c].x; imin = ci[c].x; }
        if (cv[c].y < vmin || (cv[c].y == vmin && ci[c].y < imin)) { vmin = cv[c].y; imin = ci[c].y; }
    }
    float thr = vmin + MARGIN;
    int cnt = 0; bool susp = false;
#pragma unroll
    for (int c = 0; c < 16; c++) {
        if (cv[c].x <= thr) cnt++;
        if (cv[c].y <= thr) { cnt++; susp = true; }  // half-block 2nd in margin -> hidden 3rd risk
    }
    if (cnt <= 1)       g_idx[row] = imin;
    else if (!susp)     g_wlA[atomicAdd(&g_nA, 1)] = row;
    else                g_wlB[atomicAdd(&g_nB, 1)] = row;
}

// ---------------- refine: exact serial-fma arbitration over candidates ------
__global__ void __launch_bounds__(256) k_refine(const float* __restrict__ inp,
                                                const float* __restrict__ emb) {
    int nA = g_nA;
    int lane = threadIdx.x & 31;
    int gw = (blockIdx.x * blockDim.x + threadIdx.x) >> 5;
    int nw = (gridDim.x * blockDim.x) >> 5;
    for (int w = gw; w < nA; w += nw) {
        int row = g_wlA[w];
        float2 c = g_cv[row * 16 + (lane >> 1)];
        int2  ii = g_ci[row * 16 + (lane >> 1)];
        float v   = (lane & 1) ? c.y  : c.x;
        int   idx = (lane & 1) ? ii.y : ii.x;
        float vm = v;
#pragma unroll
        for (int off = 16; off; off >>= 1)
            vm = fminf(vm, __shfl_xor_sync(0xffffffffu, vm, off));
        bool active = (v <= vm + MARGIN);

        float dist = BIGF;
        if (active) {
            int b = row >> 10, hw = row & 1023;
            const float* fp = inp + (size_t)b * B_STRIDE + hw;
            const float* ep = emb + (size_t)idx * 256;
            float acc = 0.f;
            for (int k = 0; k < 256; k++)                 // ascending-k serial fma (R2 order)
                acc = fmaf(fp[(size_t)k * 1024], ep[k], acc);
            dist = distf(g_nf[row], g_ne[idx], acc);
        } else {
            idx = 1 << 30;
        }
#pragma unroll
        for (int off = 16; off; off >>= 1) {
            float od = __shfl_xor_sync(0xffffffffu, dist, off);
            int   oi = __shfl_xor_sync(0xffffffffu, idx,  off);
            if (od < dist || (od == dist && oi < idx)) { dist = od; idx = oi; }
        }
        if (lane == 0) g_idx[row] = idx;
    }
}

// ---------------- fullscan: exact serial-fma over all 1024 codes ------------
__global__ void __launch_bounds__(256) k_fullscan(const float* __restrict__ inp,
                                                  const float* __restrict__ emb) {
    __shared__ float sf[256];
    __shared__ float svv[8];
    __shared__ int   sii[8];
    int nB = g_nB;
    int tid = threadIdx.x, lane = tid & 31, wid = tid >> 5;
    for (int w = blockIdx.x; w < nB; w += gridDim.x) {
        int row = g_wlB[w];
        int b = row >> 10, hw = row & 1023;
        sf[tid] = inp[(size_t)b * B_STRIDE + (size_t)tid * 1024 + hw];
        __syncthreads();
        float nfv = g_nf[row];
        float bv = BIGF; int bi = 1 << 30;
        for (int j = 0; j < 4; j++) {
            int c = tid * 4 + j;
            const float* ep = emb + (size_t)c * 256;
            float acc = 0.f;
            for (int k = 0; k < 256; k++)
                acc = fmaf(sf[k], ep[k], acc);
            float d = distf(nfv, g_ne[c], acc);
            if (d < bv || (d == bv && c < bi)) { bv = d; bi = c; }
        }
#pragma unroll
        for (int off = 16; off; off >>= 1) {
            float ov = __shfl_xor_sync(0xffffffffu, bv, off);
            int   oi = __shfl_xor_sync(0xffffffffu, bi, off);
            if (ov < bv || (ov == bv && oi < bi)) { bv = ov; bi = oi; }
        }
        if (lane == 0) { svv[wid] = bv; sii[wid] = bi; }
        __syncthreads();
        if (tid == 0) {
            float fv = svv[0]; int fi = sii[0];
#pragma unroll
            for (int i = 1; i < 8; i++)
                if (svv[i] < fv || (svv[i] == fv && sii[i] < fi)) { fv = svv[i]; fi = sii[i]; }
            g_idx[row] = fi;
        }
        __syncthreads();
    }
}

// ---------------- histogram ----------------
__global__ void k_hist() {
    __shared__ int sc[KCODES];
    int tid = threadIdx.x;
    sc[tid] = 0;
    __syncthreads();
    int idx = g_idx[blockIdx.x * 1024 + tid];
    atomicAdd(&sc[idx], 1);
    __syncthreads();
    if (sc[tid]) atomicAdd(&g_counts[tid], sc[tid]);
}

// ---------------- gather + outputs + enc zero + loss ----------------
__global__ void __launch_bounds__(256) k_out(const float* __restrict__ inp,
                                             const float* __restrict__ emb,
                                             float* __restrict__ out) {
    __shared__ int    sidx[32];
    __shared__ float  qs[32][257];
    __shared__ double sred[8];

    int tid = threadIdx.x;
    int rBase = blockIdx.x << 5;

    {
        float2* z = reinterpret_cast<float2*>(out + OFF_ENC + (long long)rBase * 1024);
        float2 zz = make_float2(0.f, 0.f);
#pragma unroll
        for (int i = 0; i < 64; i++) z[tid + (i << 8)] = zz;
    }
    if (tid < 32) sidx[tid] = g_idx[rBase + tid];
    __syncthreads();

    for (int r = 0; r < 32; r++) {
        float v = emb[(size_t)sidx[r] * 256 + tid];
        qs[r][tid] = v;
        out[OFF_QF + (long long)(rBase + r) * 256 + tid] = v;
    }
    if (tid < 32)
        out[OFF_ENC + (long long)(rBase + tid) * 1024 + sidx[tid]] = 1.0f;
    __syncthreads();

    int b = rBase >> 10, hw0 = rBase & 1023;
    int r = tid & 31, dg = tid >> 5;
    const float* ibase = inp + (size_t)b * B_STRIDE + hw0 + r;
    float*       obase = out + OFF_QOUT + (long long)b * B_STRIDE + hw0 + r;

    double lacc = 0.0;
    for (int db = 0; db < 32; db++) {
        int d = (db << 3) + dg;
        float x = ibase[(size_t)d * 1024];
        float q = qs[r][d];
        float diff = __fsub_rn(q, x);
        obase[(long long)d * 1024] = __fadd_rn(x, diff);
        lacc += (double)__fmul_rn(diff, diff);
    }
#pragma unroll
    for (int off = 16; off; off >>= 1) lacc += __shfl_down_sync(0xffffffffu, lacc, off);
    if ((tid & 31) == 0) sred[tid >> 5] = lacc;
    __syncthreads();
    if (tid == 0) {
        double s = 0.0;
#pragma unroll
        for (int i = 0; i < 8; i++) s += sred[i];
        atomicAdd(&g_loss_acc, s);
    }
}

// ---------------- finalize ----------------
__global__ void k_final(float* __restrict__ out) {
    __shared__ double sred[32];
    int tid = threadIdx.x;
    int c = g_counts[tid];
    float pf = __fmul_rn((float)c, 1.0f / 65536.0f);
    float lf = logf(__fadd_rn(pf, 1e-10f));
    double term = (double)__fmul_rn(pf, lf);
#pragma unroll
    for (int off = 16; off; off >>= 1) term += __shfl_down_sync(0xffffffffu, term, off);
    if ((tid & 31) == 0) sred[tid >> 5] = term;
    __syncthreads();
    if (tid == 0) {
        double s = 0.0;
#pragma unroll
        for (int i = 0; i < 32; i++) s += sred[i];
        out[OFF_PERP] = expf((float)(-s));
        double mse = g_loss_acc * (1.0 / 16777216.0);
        float  m   = (float)mse;
        out[OFF_LOSS] = __fadd_rn(m, __fmul_rn(0.25f, m));
    }
}

// ---------------- launch ----------------
extern "C" void kernel_launch(void* const* d_in, const int* in_sizes, int n_in,
                              void* d_out, int out_size) {
    const float* inp = (const float*)d_in[0];
    const float* emb = (const float*)d_in[1];
    if (n_in >= 2 && in_sizes[0] == KCODES * DDIM) {
        const float* t = inp; inp = emb; emb = t;
    }
    float* out = (float*)d_out;

    cudaFuncSetAttribute(k_gemm, cudaFuncAttributeMaxDynamicSharedMemorySize,
                         SM_FLOATS * 4);

    k_init    <<<4, 256>>>();
    k_ne      <<<128, 256>>>(emb);
    k_nf      <<<256, 256>>>(inp);
    k_gemm    <<<dim3(8, 512), 256, SM_FLOATS * 4>>>(inp, emb);
    k_pick    <<<256, 256>>>();
    k_refine  <<<64, 256>>>(inp, emb);
    k_fullscan<<<32, 256>>>(inp, emb);
    k_hist    <<<64, 1024>>>();
    k_out     <<<2048, 256>>>(inp, emb, out);
    k_final   <<<1, 1024>>>(out);
}

// round 17
// speedup vs baseline: 1.0059x; 1.0059x over previous
#include <cuda_runtime.h>
#include <cstdint>

#define N_ROWS   65536
#define KCODES   1024
#define DDIM     256
#define B_STRIDE 262144

#define OFF_LOSS 0ll
#define OFF_QOUT 1ll
#define OFF_PERP 16777217ll
#define OFF_ENC  16777218ll
#define OFF_QF   83886082ll

#define MARGIN 1.0e-4f
#define BIGF   3.4e38f

// ---------------- device scratch ----------------
__device__ float  g_nf[N_ROWS];
__device__ float  g_ne[KCODES];
__device__ int    g_idx[N_ROWS];
__device__ int    g_counts[KCODES];
__device__ double g_loss_acc;
__device__ float2 g_cv[N_ROWS * 16];  // per-row, per 64-code half-block top-2 dists
__device__ int2   g_ci[N_ROWS * 16];  // matching code indices
__device__ int    g_wlA[N_ROWS];
__device__ int    g_wlB[N_ROWS];
__device__ int    g_nA, g_nB;

__device__ __forceinline__ uint32_t cvt_tf32(float x) {
    uint32_t r; asm("cvt.rna.tf32.f32 %0, %1;" : "=r"(r) : "f"(x)); return r;
}
__device__ __forceinline__ void mma8(float* c, const uint32_t* a, uint32_t b0, uint32_t b1) {
    asm volatile(
        "mma.sync.aligned.m16n8k8.row.col.f32.tf32.tf32.f32 "
        "{%0,%1,%2,%3}, {%4,%5,%6,%7}, {%8,%9}, {%0,%1,%2,%3};"
        : "+f"(c[0]), "+f"(c[1]), "+f"(c[2]), "+f"(c[3])
        : "r"(a[0]), "r"(a[1]), "r"(a[2]), "r"(a[3]), "r"(b0), "r"(b1));
}
// exact distance formula — bit-identical to the proven R2 kernel
__device__ __forceinline__ float distf(float nf, float ne, float c) {
    return __fsub_rn(__fadd_rn(nf, ne), __fmul_rn(2.0f, c));
}

// ---------------- init ----------------
__global__ void k_init() {
    int g = blockIdx.x * blockDim.x + threadIdx.x;
    if (g < KCODES) g_counts[g] = 0;
    if (g == 0) { g_loss_acc = 0.0; g_nA = 0; g_nB = 0; }
}

// ---------------- ||e_k||^2 ----------------
__global__ void k_ne(const float* __restrict__ emb) {
    int w = blockIdx.x * 8 + (threadIdx.x >> 5);
    int lane = threadIdx.x & 31;
    const float* e = emb + (size_t)w * DDIM;
    float s = 0.f;
#pragma unroll
    for (int j = 0; j < 8; j++) { float v = e[lane + 32 * j]; s = __fadd_rn(s, __fmul_rn(v, v)); }
#pragma unroll
    for (int off = 16; off; off >>= 1) s = __fadd_rn(s, __shfl_down_sync(0xffffffffu, s, off));
    if (lane == 0) g_ne[w] = s;
}

// ---------------- ||f_n||^2 ----------------
__global__ void __launch_bounds__(256) k_nf(const float* __restrict__ inp) {
    int r = blockIdx.x * 256 + threadIdx.x;
    int b = r >> 10, hw = r & 1023;
    const float* p = inp + (size_t)b * B_STRIDE + hw;
    float acc[16];
#pragma unroll
    for (int j = 0; j < 16; j++) acc[j] = 0.f;
    for (int s = 0; s < 16; s++)
#pragma unroll
        for (int j = 0; j < 16; j++) {
            float v = p[(size_t)(s * 16 + j) * 1024];
            acc[j] = __fadd_rn(acc[j], __fmul_rn(v, v));
        }
#pragma unroll
    for (int s2 = 8; s2; s2 >>= 1)
#pragma unroll
        for (int j = 0; j < 8; j++)
            if (j < s2) acc[j] = __fadd_rn(acc[j], acc[j + s2]);
    g_nf[r] = acc[0];
}

// ---------------- 3xTF32 mma.sync distance-GEMM -> per-half-block top-2 -----
#define PADW 136
#define SM_FLOATS (4 * 32 * PADW)

__global__ void __launch_bounds__(256) k_gemm(const float* __restrict__ inp,
                                              const float* __restrict__ emb) {
    extern __shared__ float sm[];
    float* Ah = sm;
    float* Al = sm + 32 * PADW;
    float* Bh = sm + 2 * 32 * PADW;
    float* Bl = sm + 3 * 32 * PADW;

    const int tid = threadIdx.x, lane = tid & 31, wid = tid >> 5;
    const int wm = wid & 3, wn = wid >> 2;
    const int cb = blockIdx.x, rblk = blockIdx.y;
    const int b = (rblk * 128) >> 10, hw0 = (rblk * 128) & 1023;
    const float* aG = inp + (size_t)b * B_STRIDE + hw0;
    const float* bG = emb + (size_t)cb * 128 * 256;

    float acc[2][8][4];
#pragma unroll
    for (int mt = 0; mt < 2; mt++)
#pragma unroll
        for (int nt = 0; nt < 8; nt++)
#pragma unroll
            for (int e = 0; e < 4; e++) acc[mt][nt][e] = 0.f;

    const int lr4 = (tid & 31) << 2;
    const int lk  = tid >> 5;
    const int bn  = tid >> 1;
    const int bk0 = (tid & 1) << 4;
    const int aoff = (lane & 3) * PADW + wm * 32 + (lane >> 2);
    const int boff = (lane & 3) * PADW + wn * 64 + (lane >> 2);

    for (int kt = 0; kt < 8; kt++) {
#pragma unroll
        for (int i = 0; i < 4; i++) {
            int k = lk + i * 8;
            float4 v = *reinterpret_cast<const float4*>(
                aG + (size_t)(kt * 32 + k) * 1024 + lr4);
            uint32_t hx = cvt_tf32(v.x), hy = cvt_tf32(v.y),
                     hz = cvt_tf32(v.z), hw = cvt_tf32(v.w);
            float4 h = make_float4(__uint_as_float(hx), __uint_as_float(hy),
                                   __uint_as_float(hz), __uint_as_float(hw));
            float4 l = make_float4(
                __uint_as_float(cvt_tf32(__fsub_rn(v.x, h.x))),
                __uint_as_float(cvt_tf32(__fsub_rn(v.y, h.y))),
                __uint_as_float(cvt_tf32(__fsub_rn(v.z, h.z))),
                __uint_as_float(cvt_tf32(__fsub_rn(v.w, h.w))));
            *reinterpret_cast<float4*>(&Ah[k * PADW + lr4]) = h;
            *reinterpret_cast<float4*>(&Al[k * PADW + lr4]) = l;
        }
#pragma unroll
        for (int j = 0; j < 4; j++) {
            float4 v = *reinterpret_cast<const float4*>(
                bG + (size_t)bn * 256 + kt * 32 + bk0 + j * 4);
            int k = bk0 + j * 4;
            float fx[4] = {v.x, v.y, v.z, v.w};
#pragma unroll
            for (int e = 0; e < 4; e++) {
                uint32_t h = cvt_tf32(fx[e]);
                Bh[(k + e) * PADW + bn] = __uint_as_float(h);
                Bl[(k + e) * PADW + bn] =
                    __uint_as_float(cvt_tf32(__fsub_rn(fx[e], __uint_as_float(h))));
            }
        }
        __syncthreads();
#pragma unroll
        for (int k8 = 0; k8 < 4; k8++) {
            const int kb = k8 * 8 * PADW;
            uint32_t ah[2][4], al[2][4];
#pragma unroll
            for (int mt = 0; mt < 2; mt++) {
                int o = kb + aoff + mt * 16;
                ah[mt][0] = __float_as_uint(Ah[o]);
                ah[mt][1] = __float_as_uint(Ah[o + 8]);
                ah[mt][2] = __float_as_uint(Ah[o + 4 * PADW]);
                ah[mt][3] = __float_as_uint(Ah[o + 4 * PADW + 8]);
                al[mt][0] = __float_as_uint(Al[o]);
                al[mt][1] = __float_as_uint(Al[o + 8]);
                al[mt][2] = __float_as_uint(Al[o + 4 * PADW]);
                al[mt][3] = __float_as_uint(Al[o + 4 * PADW + 8]);
            }
#pragma unroll
            for (int nt = 0; nt < 8; nt++) {
                int o = kb + boff + nt * 8;
                uint32_t bh0 = __float_as_uint(Bh[o]);
                uint32_t bh1 = __float_as_uint(Bh[o + 4 * PADW]);
                uint32_t bl0 = __float_as_uint(Bl[o]);
                uint32_t bl1 = __float_as_uint(Bl[o + 4 * PADW]);
#pragma unroll
                for (int mt = 0; mt < 2; mt++) {
                    mma8(acc[mt][nt], ah[mt], bh0, bh1);
                    mma8(acc[mt][nt], al[mt], bh0, bh1);
                    mma8(acc[mt][nt], ah[mt], bl0, bl1);
                }
            }
        }
        __syncthreads();
    }

    float* sNe = sm;
    if (tid < 128) sNe[tid] = g_ne[cb * 128 + tid];
    __syncthreads();

    // epilogue: per-row top-2 over THIS warp's 64-code half; slot keyed by
    // (cb, wn) so the two column-half warps never collide (R10 race fix).
#pragma unroll
    for (int mt = 0; mt < 2; mt++)
#pragma unroll
        for (int half = 0; half < 2; half++) {
            int rl   = wm * 32 + mt * 16 + (lane >> 2) + half * 8;
            int grow = rblk * 128 + rl;
            float nfv = g_nf[grow];
            float v1 = BIGF, v2 = BIGF;
            int   i1 = 1 << 30, i2 = 1 << 30;
#pragma unroll
            for (int nt = 0; nt < 8; nt++)
#pragma unroll
                for (int e = 0; e < 2; e++) {
                    int cl = wn * 64 + nt * 8 + (lane & 3) * 2 + e;
                    float s = distf(nfv, sNe[cl], acc[mt][nt][half * 2 + e]);
                    int   c = cb * 128 + cl;
                    if (s < v1)      { v2 = v1; i2 = i1; v1 = s; i1 = c; }
                    else if (s < v2) { v2 = s; i2 = c; }
                }
#pragma unroll
            for (int off = 1; off < 4; off <<= 1) {
                float w1 = __shfl_down_sync(0xffffffffu, v1, off, 4);
                float w2 = __shfl_down_sync(0xffffffffu, v2, off, 4);
                int   j1 = __shfl_down_sync(0xffffffffu, i1, off, 4);
                int   j2 = __shfl_down_sync(0xffffffffu, i2, off, 4);
                if (w1 < v1 || (w1 == v1 && j1 < i1)) {
                    if (v1 < w2 || (v1 == w2 && i1 < j2)) { v2 = v1; i2 = i1; }
                    else                                  { v2 = w2; i2 = j2; }
                    v1 = w1; i1 = j1;
                } else {
                    if (w1 < v2 || (w1 == v2 && j1 < i2)) { v2 = w1; i2 = j1; }
                }
            }
            if ((lane & 3) == 0) {
                int slot = grow * 16 + cb * 2 + wn;
                g_cv[slot] = make_float2(v1, v2);
                g_ci[slot] = make_int2(i1, i2);
            }
        }
}

// ---------------- pick: resolve unambiguous rows, build worklists -----------
__global__ void __launch_bounds__(256) k_pick() {
    int row = blockIdx.x * 256 + threadIdx.x;
    float vmin = BIGF; int imin = 1 << 30;
    float2 cv[16]; int2 ci[16];
#pragma unroll
    for (int c = 0; c < 16; c++) { cv[c] = g_cv[row * 16 + c]; ci[c] = g_ci[row * 16 + c]; }
#pragma unroll
    for (int c = 0; c < 16; c++) {
        if (cv[c].x < vmin || (cv[c].x == vmin && ci[c].x < imin)) { vmin = cv[c].x; imin = ci[c].x; }
        if (cv[c].y < vmin || (cv[c].y == vmin && ci[c].y < imin)) { vmin = cv[c].y; imin = ci[c].y; }
    }
    float thr = vmin + MARGIN;
    int cnt = 0; bool susp = false;
#pragma unroll
    for (int c = 0; c < 16; c++) {
        if (cv[c].x <= thr) cnt++;
        if (cv[c].y <= thr) { cnt++; susp = true; }  // half-block 2nd in margin -> hidden 3rd risk
    }
    if (cnt <= 1)       g_idx[row] = imin;
    else if (!susp)     g_wlA[atomicAdd(&g_nA, 1)] = row;
    else                g_wlB[atomicAdd(&g_nB, 1)] = row;
}

// ---------------- refine: exact serial-fma arbitration over candidates ------
__global__ void __launch_bounds__(256) k_refine(const float* __restrict__ inp,
                                                const float* __restrict__ emb) {
    int nA = g_nA;
    int lane = threadIdx.x & 31;
    int gw = (blockIdx.x * blockDim.x + threadIdx.x) >> 5;
    int nw = (gridDim.x * blockDim.x) >> 5;
    for (int w = gw; w < nA; w += nw) {
        int row = g_wlA[w];
        float2 c = g_cv[row * 16 + (lane >> 1)];
        int2  ii = g_ci[row * 16 + (lane >> 1)];
        float v   = (lane & 1) ? c.y  : c.x;
        int   idx = (lane & 1) ? ii.y : ii.x;
        float vm = v;
#pragma unroll
        for (int off = 16; off; off >>= 1)
            vm = fminf(vm, __shfl_xor_sync(0xffffffffu, vm, off));
        bool active = (v <= vm + MARGIN);

        float dist = BIGF;
        if (active) {
            int b = row >> 10, hw = row & 1023;
            const float* fp = inp + (size_t)b * B_STRIDE + hw;
            const float* ep = emb + (size_t)idx * 256;
            float acc = 0.f;
            for (int k = 0; k < 256; k++)                 // ascending-k serial fma (R2 order)
                acc = fmaf(fp[(size_t)k * 1024], ep[k], acc);
            dist = distf(g_nf[row], g_ne[idx], acc);
        } else {
            idx = 1 << 30;
        }
#pragma unroll
        for (int off = 16; off; off >>= 1) {
            float od = __shfl_xor_sync(0xffffffffu, dist, off);
            int   oi = __shfl_xor_sync(0xffffffffu, idx,  off);
            if (od < dist || (od == dist && oi < idx)) { dist = od; idx = oi; }
        }
        if (lane == 0) g_idx[row] = idx;
    }
}

// ---------------- fullscan: exact serial-fma over all 1024 codes ------------
__global__ void __launch_bounds__(256) k_fullscan(const float* __restrict__ inp,
                                                  const float* __restrict__ emb) {
    __shared__ float sf[256];
    __shared__ float svv[8];
    __shared__ int   sii[8];
    int nB = g_nB;
    int tid = threadIdx.x, lane = tid & 31, wid = tid >> 5;
    for (int w = blockIdx.x; w < nB; w += gridDim.x) {
        int row = g_wlB[w];
        int b = row >> 10, hw = row & 1023;
        sf[tid] = inp[(size_t)b * B_STRIDE + (size_t)tid * 1024 + hw];
        __syncthreads();
        float nfv = g_nf[row];
        float bv = BIGF; int bi = 1 << 30;
        for (int j = 0; j < 4; j++) {
            int c = tid * 4 + j;
            const float* ep = emb + (size_t)c * 256;
            float acc = 0.f;
            for (int k = 0; k < 256; k++)
                acc = fmaf(sf[k], ep[k], acc);
            float d = distf(nfv, g_ne[c], acc);
            if (d < bv || (d == bv && c < bi)) { bv = d; bi = c; }
        }
#pragma unroll
        for (int off = 16; off; off >>= 1) {
            float ov = __shfl_xor_sync(0xffffffffu, bv, off);
            int   oi = __shfl_xor_sync(0xffffffffu, bi, off);
            if (ov < bv || (ov == bv && oi < bi)) { bv = ov; bi = oi; }
        }
        if (lane == 0) { svv[wid] = bv; sii[wid] = bi; }
        __syncthreads();
        if (tid == 0) {
            float fv = svv[0]; int fi = sii[0];
#pragma unroll
            for (int i = 1; i < 8; i++)
                if (svv[i] < fv || (svv[i] == fv && sii[i] < fi)) { fv = svv[i]; fi = sii[i]; }
            g_idx[row] = fi;
        }
        __syncthreads();
    }
}

// ---------------- histogram ----------------
__global__ void k_hist() {
    __shared__ int sc[KCODES];
    int tid = threadIdx.x;
    sc[tid] = 0;
    __syncthreads();
    int idx = g_idx[blockIdx.x * 1024 + tid];
    atomicAdd(&sc[idx], 1);
    __syncthreads();
    if (sc[tid]) atomicAdd(&g_counts[tid], sc[tid]);
}

// ---------------- gather + outputs + enc zero + loss ----------------
__global__ void __launch_bounds__(256) k_out(const float* __restrict__ inp,
                                             const float* __restrict__ emb,
                                             float* __restrict__ out) {
    __shared__ int    sidx[32];
    __shared__ float  qs[32][257];
    __shared__ double sred[8];

    int tid = threadIdx.x;
    int rBase = blockIdx.x << 5;

    {
        float2* z = reinterpret_cast<float2*>(out + OFF_ENC + (long long)rBase * 1024);
        float2 zz = make_float2(0.f, 0.f);
#pragma unroll
        for (int i = 0; i < 64; i++) z[tid + (i << 8)] = zz;
    }
    if (tid < 32) sidx[tid] = g_idx[rBase + tid];
    __syncthreads();

    for (int r = 0; r < 32; r++) {
        float v = emb[(size_t)sidx[r] * 256 + tid];
        qs[r][tid] = v;
        out[OFF_QF + (long long)(rBase + r) * 256 + tid] = v;
    }
    if (tid < 32)
        out[OFF_ENC + (long long)(rBase + tid) * 1024 + sidx[tid]] = 1.0f;
    __syncthreads();

    int b = rBase >> 10, hw0 = rBase & 1023;
    int r = tid & 31, dg = tid >> 5;
    const float* ibase = inp + (size_t)b * B_STRIDE + hw0 + r;
    float*       obase = out + OFF_QOUT + (long long)b * B_STRIDE + hw0 + r;

    double lacc = 0.0;
    for (int db = 0; db < 32; db++) {
        int d = (db << 3) + dg;
        float x = ibase[(size_t)d * 1024];
        float q = qs[r][d];
        float diff = __fsub_rn(q, x);
        obase[(long long)d * 1024] = __fadd_rn(x, diff);
        lacc += (double)__fmul_rn(diff, diff);
    }
#pragma unroll
    for (int off = 16; off; off >>= 1) lacc += __shfl_down_sync(0xffffffffu, lacc, off);
    if ((tid & 31) == 0) sred[tid >> 5] = lacc;
    __syncthreads();
    if (tid == 0) {
        double s = 0.0;
#pragma unroll
        for (int i = 0; i < 8; i++) s += sred[i];
        atomicAdd(&g_loss_acc, s);
    }
}

// ---------------- finalize ----------------
__global__ void k_final(float* __restrict__ out) {
    __shared__ double sred[32];
    int tid = threadIdx.x;
    int c = g_counts[tid];
    float pf = __fmul_rn((float)c, 1.0f / 65536.0f);
    float lf = logf(__fadd_rn(pf, 1e-10f));
    double term = (double)__fmul_rn(pf, lf);
#pragma unroll
    for (int off = 16; off; off >>= 1) term += __shfl_down_sync(0xffffffffu, term, off);
    if ((tid & 31) == 0) sred[tid >> 5] = term;
    __syncthreads();
    if (tid == 0) {
        double s = 0.0;
#pragma unroll
        for (int i = 0; i < 32; i++) s += sred[i];
        out[OFF_PERP] = expf((float)(-s));
        double mse = g_loss_acc * (1.0 / 16777216.0);
        float  m   = (float)mse;
        out[OFF_LOSS] = __fadd_rn(m, __fmul_rn(0.25f, m));
    }
}

// ---------------- launch ----------------
extern "C" void kernel_launch(void* const* d_in, const int* in_sizes, int n_in,
                              void* d_out, int out_size) {
    const float* inp = (const float*)d_in[0];
    const float* emb = (const float*)d_in[1];
    if (n_in >= 2 && in_sizes[0] == KCODES * DDIM) {
        const float* t = inp; inp = emb; emb = t;
    }
    float* out = (float*)d_out;

    cudaFuncSetAttribute(k_gemm, cudaFuncAttributeMaxDynamicSharedMemorySize,
                         SM_FLOATS * 4);

    k_init    <<<4, 256>>>();
    k_ne      <<<128, 256>>>(emb);
    k_nf      <<<256, 256>>>(inp);
    k_gemm    <<<dim3(8, 512), 256, SM_FLOATS * 4>>>(inp, emb);
    k_pick    <<<256, 256>>>();
    k_refine  <<<64, 256>>>(inp, emb);
    k_fullscan<<<32, 256>>>(inp, emb);
    k_hist    <<<64, 1024>>>();
    k_out     <<<2048, 256>>>(inp, emb, out);
    k_final   <<<1, 1024>>>(out);
}